// round 10
// baseline (speedup 1.0000x reference)
#include <cuda_runtime.h>
#include <cuda_bf16.h>
#include <math.h>
#include <cstdint>

#define BB   2
#define LL   2048
#define DM   1024
#define HH   16
#define DKK  64
#define MROWS (BB*LL)

typedef __nv_bfloat16 bf16;

// ---------------- scratch ----------------
__device__ bf16 g_xhi[(size_t)MROWS*DM];
__device__ bf16 g_xlo[(size_t)MROWS*DM];
__device__ bf16 g_wqhi[(size_t)DM*DM];
__device__ bf16 g_wqlo[(size_t)DM*DM];
__device__ bf16 g_wkhi[(size_t)DM*DM];
__device__ bf16 g_wklo[(size_t)DM*DM];
__device__ bf16 g_wvhi[(size_t)DM*DM];
__device__ bf16 g_wvlo[(size_t)DM*DM];
__device__ bf16 g_wohi[(size_t)DM*DM];
__device__ bf16 g_wolo[(size_t)DM*DM];
__device__ bf16 g_qhi[(size_t)BB*HH*LL*DKK];
__device__ bf16 g_qlo[(size_t)BB*HH*LL*DKK];
__device__ bf16 g_khi[(size_t)BB*HH*LL*DKK];
__device__ bf16 g_klo[(size_t)BB*HH*LL*DKK];
__device__ bf16 g_vhi[(size_t)BB*HH*LL*DKK];
__device__ bf16 g_vlo[(size_t)BB*HH*LL*DKK];
__device__ bf16 g_chi[(size_t)MROWS*DM];
__device__ bf16 g_clo[(size_t)MROWS*DM];

// ---------------- helpers ----------------
__device__ __forceinline__ uint32_t smem_u32(const void* p) {
    uint32_t a;
    asm("{ .reg .u64 t; cvta.to.shared.u64 t, %1; cvt.u32.u64 %0, t; }" : "=r"(a) : "l"(p));
    return a;
}
__device__ __forceinline__ void ldsm4(uint32_t* r, uint32_t a) {
    asm volatile("ldmatrix.sync.aligned.m8n8.x4.shared.b16 {%0,%1,%2,%3}, [%4];"
        : "=r"(r[0]), "=r"(r[1]), "=r"(r[2]), "=r"(r[3]) : "r"(a));
}
__device__ __forceinline__ void ldsm4t(uint32_t* r, uint32_t a) {
    asm volatile("ldmatrix.sync.aligned.m8n8.x4.trans.shared.b16 {%0,%1,%2,%3}, [%4];"
        : "=r"(r[0]), "=r"(r[1]), "=r"(r[2]), "=r"(r[3]) : "r"(a));
}
__device__ __forceinline__ void mma16816(float* c, const uint32_t* a, uint32_t b0, uint32_t b1) {
    asm volatile(
        "mma.sync.aligned.m16n8k16.row.col.f32.bf16.bf16.f32 "
        "{%0,%1,%2,%3}, {%4,%5,%6,%7}, {%8,%9}, {%0,%1,%2,%3};"
        : "+f"(c[0]), "+f"(c[1]), "+f"(c[2]), "+f"(c[3])
        : "r"(a[0]), "r"(a[1]), "r"(a[2]), "r"(a[3]), "r"(b0), "r"(b1));
}
__device__ __forceinline__ void cp16(uint32_t dst, const void* src) {
    asm volatile("cp.async.cg.shared.global [%0], [%1], 16;" :: "r"(dst), "l"(src));
}
#define CP_COMMIT() asm volatile("cp.async.commit_group;" ::: "memory")
#define CP_WAIT0()  asm volatile("cp.async.wait_group 0;" ::: "memory")

__device__ __forceinline__ uint32_t pack_bf16x2(bf16 lo, bf16 hi) {
    __nv_bfloat162 t{lo, hi};
    return *reinterpret_cast<uint32_t*>(&t);
}
__device__ __forceinline__ void store_hilo(bf16* Hi, bf16* Lo, size_t idx, float x, float y) {
    bf16 hx = __float2bfloat16(x), hy = __float2bfloat16(y);
    __nv_bfloat162 hp{hx, hy};
    *reinterpret_cast<__nv_bfloat162*>(&Hi[idx]) = hp;
    __nv_bfloat162 lp{__float2bfloat16(x - __bfloat162float(hx)),
                      __float2bfloat16(y - __bfloat162float(hy))};
    *reinterpret_cast<__nv_bfloat162*>(&Lo[idx]) = lp;
}

extern __shared__ char dynsmem[];

// ---------------------------------------------------------------------------
// split: fp32 -> (scale*) bf16 hi + bf16 lo
// ---------------------------------------------------------------------------
__global__ __launch_bounds__(256) void split_kernel(
    const float* __restrict__ in, bf16* __restrict__ hi, bf16* __restrict__ lo,
    int n4, float scale)
{
    int i = blockIdx.x * blockDim.x + threadIdx.x;
    if (i >= n4) return;
    float4 v = ((const float4*)in)[i];
    v.x *= scale; v.y *= scale; v.z *= scale; v.w *= scale;
    bf16 h0 = __float2bfloat16(v.x), h1 = __float2bfloat16(v.y);
    bf16 h2 = __float2bfloat16(v.z), h3 = __float2bfloat16(v.w);
    ((__nv_bfloat162*)hi)[2*i]   = {h0, h1};
    ((__nv_bfloat162*)hi)[2*i+1] = {h2, h3};
    ((__nv_bfloat162*)lo)[2*i]   = {__float2bfloat16(v.x - __bfloat162float(h0)),
                                    __float2bfloat16(v.y - __bfloat162float(h1))};
    ((__nv_bfloat162*)lo)[2*i+1] = {__float2bfloat16(v.z - __bfloat162float(h2)),
                                    __float2bfloat16(v.w - __bfloat162float(h3))};
}

// ---------------------------------------------------------------------------
// HMMA bf16-split NT GEMM, cp.async 2-stage pipeline, K-chunk 32.
// Block 128x128, 8 warps (2M x 4N). 3 products, fp32 accum.
// ---------------------------------------------------------------------------
#define GP 80                       // gemm smem row stride bytes (32 bf16 + pad)
#define G_PLANE (128*GP)            // 10240 B
#define G_STAGE (4*G_PLANE)         // 40960 B
#define GEMM_SMEM (2*G_STAGE)       // 81920 B

__global__ __launch_bounds__(256, 2) void gemm_tc(
    const bf16* __restrict__ Ahi, const bf16* __restrict__ Alo,
    const bf16* __restrict__ Whi, const bf16* __restrict__ Wlo,
    float* __restrict__ Cf, bf16* __restrict__ Chi, bf16* __restrict__ Clo,
    int mode)
{
    const uint32_t smb = smem_u32(dynsmem);
    const int tid = threadIdx.x, lane = tid & 31, wid = tid >> 5;
    const int wm = wid >> 2, wn = wid & 3;
    const int m0 = blockIdx.y * 128, n0 = blockIdx.x * 128;
    const int r0 = lane >> 2, cq = (lane & 3) * 2;

    const bf16* plane_src[4] = {Ahi, Alo, Whi, Wlo};
    const int   plane_row0[4] = {m0, m0, n0, n0};

    // one chunk = 4 planes x 128 rows x 64 bytes (4 segs of 16B) = 2048 cp16
    auto issue_chunk = [&](int kc) {
        const uint32_t sbase = smb + (kc & 1) * G_STAGE;
        #pragma unroll
        for (int it = 0; it < 8; it++) {
            const int idx = tid + it * 256;        // 0..2047
            const int pl  = idx >> 9;
            const int r   = (idx >> 2) & 127;
            const int seg = idx & 3;
            cp16(sbase + pl * G_PLANE + r * GP + seg * 16,
                 plane_src[pl] + (size_t)(plane_row0[pl] + r) * DM + kc * 32 + seg * 8);
        }
    };

    float acc[4][4][4];
    #pragma unroll
    for (int i = 0; i < 4; i++)
        #pragma unroll
        for (int j = 0; j < 4; j++)
            #pragma unroll
            for (int q = 0; q < 4; q++) acc[i][j][q] = 0.f;

    issue_chunk(0);
    CP_COMMIT();

    for (int kc = 0; kc < 32; kc++) {
        CP_WAIT0();
        __syncthreads();
        if (kc + 1 < 32) { issue_chunk(kc + 1); CP_COMMIT(); }

        const uint32_t sbase = smb + (kc & 1) * G_STAGE;
        #pragma unroll
        for (int t = 0; t < 2; t++) {
            const uint32_t qoff = (lane & 15) * GP + (lane >> 4) * 16 + t * 32;
            uint32_t ah[4][4], al[4][4];
            #pragma unroll
            for (int mf = 0; mf < 4; mf++) {
                const uint32_t ra = (wm*64 + mf*16) * GP + qoff;
                ldsm4(ah[mf], sbase + 0*G_PLANE + ra);
                ldsm4(al[mf], sbase + 1*G_PLANE + ra);
            }
            #pragma unroll
            for (int jp = 0; jp < 2; jp++) {
                const uint32_t rb = (wn*32 + jp*16) * GP + qoff;
                uint32_t bh[4], bl[4];
                ldsm4(bh, sbase + 2*G_PLANE + rb);
                ldsm4(bl, sbase + 3*G_PLANE + rb);
                #pragma unroll
                for (int mf = 0; mf < 4; mf++) {
                    mma16816(acc[mf][2*jp],   ah[mf], bh[0], bh[2]);
                    mma16816(acc[mf][2*jp+1], ah[mf], bh[1], bh[3]);
                    mma16816(acc[mf][2*jp],   ah[mf], bl[0], bl[2]);
                    mma16816(acc[mf][2*jp+1], ah[mf], bl[1], bl[3]);
                    mma16816(acc[mf][2*jp],   al[mf], bh[0], bh[2]);
                    mma16816(acc[mf][2*jp+1], al[mf], bh[1], bh[3]);
                }
            }
        }
    }

    #pragma unroll
    for (int mf = 0; mf < 4; mf++) {
        const int mr = m0 + wm*64 + mf*16 + r0;
        #pragma unroll
        for (int jf = 0; jf < 4; jf++) {
            const int col = n0 + wn*32 + jf*8 + cq;
            if (mode == 0) {
                *(float2*)&Cf[(size_t)mr * DM + col] =
                    make_float2(acc[mf][jf][0], acc[mf][jf][1]);
                *(float2*)&Cf[(size_t)(mr+8) * DM + col] =
                    make_float2(acc[mf][jf][2], acc[mf][jf][3]);
            } else {
                const int h = col >> 6, d = col & 63;
                const int b0_ = mr >> 11, l0 = mr & 2047;
                store_hilo(Chi, Clo, (((size_t)(b0_*HH + h) * LL + l0) * DKK + d),
                           acc[mf][jf][0], acc[mf][jf][1]);
                const int mr1 = mr + 8;
                const int b1_ = mr1 >> 11, l1 = mr1 & 2047;
                store_hilo(Chi, Clo, (((size_t)(b1_*HH + h) * LL + l1) * DKK + d),
                           acc[mf][jf][2], acc[mf][jf][3]);
            }
        }
    }
}

// ---------------------------------------------------------------------------
// HMMA flash attention, bf16-split, cp.async 2-stage KV pipeline.
// Q pre-scaled by 1/sqrt(dk) (folded into Wq). Bias+mask preloaded into the
// S accumulators before the QK^T MMA.
// Grid (L/128, B*H), 8 warps; warp = 16 q-rows x 64-key tile.
// NOTE: rows are 64 bf16 = 128 bytes = 8 x 16B segments.
// ---------------------------------------------------------------------------
#define AP 144                      // attn smem row stride bytes (64 bf16 + pad)
#define AQ_PLANE (128*AP)           // 18432 B
#define AKV_PLANE (64*AP)           // 9216 B
#define AKV_STAGE (4*AKV_PLANE)     // 36864 B
#define ATT_SMEM (2*AQ_PLANE + 2*AKV_STAGE)  // 110592 B

__global__ __launch_bounds__(256, 2) void attn_tc(
    const bf16* __restrict__ Qhi, const bf16* __restrict__ Qlo,
    const bf16* __restrict__ Khi, const bf16* __restrict__ Klo,
    const bf16* __restrict__ Vhi, const bf16* __restrict__ Vlo,
    const float* __restrict__ bias, const float* __restrict__ mask,
    bf16* __restrict__ Chi, bf16* __restrict__ Clo)
{
    const uint32_t smb = smem_u32(dynsmem);
    const int tid = threadIdx.x, lane = tid & 31, wid = tid >> 5;
    const int bh = blockIdx.y;
    const int b  = bh >> 4, h = bh & 15;
    const int q0 = blockIdx.x * 128;
    const int wr = wid * 16;
    const int r0 = lane >> 2, cq = (lane & 3) * 2;

    const bf16* Qpl[2] = {Qhi + (size_t)bh * LL * DKK, Qlo + (size_t)bh * LL * DKK};
    const bf16* KVpl[4] = {Khi + (size_t)bh * LL * DKK, Klo + (size_t)bh * LL * DKK,
                           Vhi + (size_t)bh * LL * DKK, Vlo + (size_t)bh * LL * DKK};
    const float* brow0 = bias + ((size_t)bh * LL + (q0 + wr + r0)) * LL;
    const float* brow1 = brow0 + 8 * (size_t)LL;
    const float* maskb = mask + (size_t)b * LL;

    // one KV tile = 4 planes x 64 rows x 8 segs(16B) = 2048 cp16
    auto issue_kv = [&](int kt) {
        const uint32_t sbase = smb + 2*AQ_PLANE + (kt & 1) * AKV_STAGE;
        const int k0 = kt * 64;
        #pragma unroll
        for (int it = 0; it < 8; it++) {
            const int idx = tid + it * 256;       // 0..2047
            const int pl  = idx >> 9;
            const int r   = (idx >> 3) & 63;
            const int seg = idx & 7;
            cp16(sbase + pl * AKV_PLANE + r * AP + seg * 16,
                 KVpl[pl] + (size_t)(k0 + r) * DKK + seg * 8);
        }
    };

    // prologue: Q (2 planes x 128 rows x 8 segs = 2048) + KV tile 0
    #pragma unroll
    for (int it = 0; it < 8; it++) {
        const int idx = tid + it * 256;           // 0..2047
        const int pl  = idx >> 10;
        const int r   = (idx >> 3) & 127;
        const int seg = idx & 7;
        cp16(smb + pl * AQ_PLANE + r * AP + seg * 16,
             Qpl[pl] + (size_t)(q0 + r) * DKK + seg * 8);
    }
    issue_kv(0);
    CP_COMMIT();

    float m_i[2] = {-1e30f, -1e30f}, l_i[2] = {0.f, 0.f};
    float oacc[8][4];
    #pragma unroll
    for (int j = 0; j < 8; j++)
        #pragma unroll
        for (int q = 0; q < 4; q++) oacc[j][q] = 0.f;

    for (int kt = 0; kt < LL/64; kt++) {
        const int k0 = kt * 64;
        CP_WAIT0();
        __syncthreads();
        if (kt + 1 < LL/64) { issue_kv(kt + 1); CP_COMMIT(); }

        const uint32_t kv = smb + 2*AQ_PLANE + (kt & 1) * AKV_STAGE;

        // ---- S init = bias + mask ----
        float sacc[8][4];
        #pragma unroll
        for (int j = 0; j < 8; j++) {
            const int kc = k0 + j*8 + cq;
            float2 bz0 = *(const float2*)&brow0[kc];
            float2 bz1 = *(const float2*)&brow1[kc];
            float2 mz  = *(const float2*)&maskb[kc];
            sacc[j][0] = bz0.x + mz.x;
            sacc[j][1] = bz0.y + mz.y;
            sacc[j][2] = bz1.x + mz.x;
            sacc[j][3] = bz1.y + mz.y;
        }

        // ---- S += Q K^T ----
        #pragma unroll
        for (int t = 0; t < 4; t++) {
            const uint32_t qoff = (lane & 15) * AP + (lane >> 4) * 16 + t * 32;
            uint32_t qa[4], ql[4];
            ldsm4(qa, smb + 0*AQ_PLANE + wr * AP + qoff);
            ldsm4(ql, smb + 1*AQ_PLANE + wr * AP + qoff);
            #pragma unroll
            for (int jp = 0; jp < 4; jp++) {
                const uint32_t rb = (jp*16) * AP + qoff;
                uint32_t kb[4], kl[4];
                ldsm4(kb, kv + 0*AKV_PLANE + rb);
                ldsm4(kl, kv + 1*AKV_PLANE + rb);
                mma16816(sacc[2*jp],   qa, kb[0], kb[2]);
                mma16816(sacc[2*jp+1], qa, kb[1], kb[3]);
                mma16816(sacc[2*jp],   qa, kl[0], kl[2]);
                mma16816(sacc[2*jp+1], qa, kl[1], kl[3]);
                mma16816(sacc[2*jp],   ql, kb[0], kb[2]);
                mma16816(sacc[2*jp+1], ql, kb[1], kb[3]);
            }
        }

        // ---- row max ----
        float mx0 = -1e30f, mx1 = -1e30f;
        #pragma unroll
        for (int j = 0; j < 8; j++) {
            mx0 = fmaxf(mx0, fmaxf(sacc[j][0], sacc[j][1]));
            mx1 = fmaxf(mx1, fmaxf(sacc[j][2], sacc[j][3]));
        }
        mx0 = fmaxf(mx0, __shfl_xor_sync(0xffffffffu, mx0, 1));
        mx0 = fmaxf(mx0, __shfl_xor_sync(0xffffffffu, mx0, 2));
        mx1 = fmaxf(mx1, __shfl_xor_sync(0xffffffffu, mx1, 1));
        mx1 = fmaxf(mx1, __shfl_xor_sync(0xffffffffu, mx1, 2));

        const float mn0 = fmaxf(m_i[0], mx0);
        const float mn1 = fmaxf(m_i[1], mx1);
        const float corr0 = __expf(m_i[0] - mn0);
        const float corr1 = __expf(m_i[1] - mn1);
        m_i[0] = mn0; m_i[1] = mn1;

        // ---- exp + split P hi/lo ----
        uint32_t ph[4][4], pl[4][4];
        float rs0 = 0.f, rs1 = 0.f;
        #pragma unroll
        for (int j = 0; j < 8; j++) {
            float p0 = __expf(sacc[j][0] - mn0);
            float p1 = __expf(sacc[j][1] - mn0);
            float p2 = __expf(sacc[j][2] - mn1);
            float p3 = __expf(sacc[j][3] - mn1);
            rs0 += p0 + p1; rs1 += p2 + p3;
            bf16 h0 = __float2bfloat16(p0), h1 = __float2bfloat16(p1);
            bf16 h2 = __float2bfloat16(p2), h3 = __float2bfloat16(p3);
            const int t = j >> 1, s = (j & 1) * 2;
            ph[t][s+0] = pack_bf16x2(h0, h1);
            ph[t][s+1] = pack_bf16x2(h2, h3);
            pl[t][s+0] = pack_bf16x2(__float2bfloat16(p0 - __bfloat162float(h0)),
                                     __float2bfloat16(p1 - __bfloat162float(h1)));
            pl[t][s+1] = pack_bf16x2(__float2bfloat16(p2 - __bfloat162float(h2)),
                                     __float2bfloat16(p3 - __bfloat162float(h3)));
        }
        rs0 += __shfl_xor_sync(0xffffffffu, rs0, 1);
        rs0 += __shfl_xor_sync(0xffffffffu, rs0, 2);
        rs1 += __shfl_xor_sync(0xffffffffu, rs1, 1);
        rs1 += __shfl_xor_sync(0xffffffffu, rs1, 2);
        l_i[0] = l_i[0] * corr0 + rs0;
        l_i[1] = l_i[1] * corr1 + rs1;

        #pragma unroll
        for (int j = 0; j < 8; j++) {
            oacc[j][0] *= corr0; oacc[j][1] *= corr0;
            oacc[j][2] *= corr1; oacc[j][3] *= corr1;
        }

        // ---- O += P V ----
        #pragma unroll
        for (int j = 0; j < 8; j++) {
            #pragma unroll
            for (int tp = 0; tp < 2; tp++) {
                const uint32_t va = (tp*32 + lane) * AP + j * 16;
                uint32_t vh[4], vl[4];
                ldsm4t(vh, kv + 2*AKV_PLANE + va);
                ldsm4t(vl, kv + 3*AKV_PLANE + va);
                mma16816(oacc[j], ph[2*tp],   vh[0], vh[1]);
                mma16816(oacc[j], ph[2*tp],   vl[0], vl[1]);
                mma16816(oacc[j], pl[2*tp],   vh[0], vh[1]);
                mma16816(oacc[j], ph[2*tp+1], vh[2], vh[3]);
                mma16816(oacc[j], ph[2*tp+1], vl[2], vl[3]);
                mma16816(oacc[j], pl[2*tp+1], vh[2], vh[3]);
            }
        }
    }

    // ---- epilogue: ctx hi/lo bf16 planes, (B*L, DM) layout ----
    const float inv0 = 1.0f / l_i[0];
    const float inv1 = 1.0f / l_i[1];
    const size_t row0 = (size_t)(b * LL + q0 + wr + r0);
    const size_t row1 = row0 + 8;
    #pragma unroll
    for (int j = 0; j < 8; j++) {
        const int col = h * DKK + j * 8 + cq;
        store_hilo(Chi, Clo, row0 * DM + col, oacc[j][0] * inv0, oacc[j][1] * inv0);
        store_hilo(Chi, Clo, row1 * DM + col, oacc[j][2] * inv1, oacc[j][3] * inv1);
    }
}

// ---------------------------------------------------------------------------
extern "C" void kernel_launch(void* const* d_in, const int* in_sizes, int n_in,
                              void* d_out, int out_size)
{
    const float* x    = (const float*)d_in[0];
    const float* Wq   = (const float*)d_in[1];
    const float* Wk   = (const float*)d_in[2];
    const float* Wv   = (const float*)d_in[3];
    const float* Wo   = (const float*)d_in[4];
    const float* bias = (const float*)d_in[5];
    const float* mask = (const float*)d_in[6];
    float* out = (float*)d_out;

    bf16 *xhi, *xlo, *wqhi, *wqlo, *wkhi, *wklo, *wvhi, *wvlo, *wohi, *wolo;
    bf16 *qhi, *qlo, *khi, *klo, *vhi, *vlo, *chi, *clo;
    cudaGetSymbolAddress((void**)&xhi, g_xhi);   cudaGetSymbolAddress((void**)&xlo, g_xlo);
    cudaGetSymbolAddress((void**)&wqhi, g_wqhi); cudaGetSymbolAddress((void**)&wqlo, g_wqlo);
    cudaGetSymbolAddress((void**)&wkhi, g_wkhi); cudaGetSymbolAddress((void**)&wklo, g_wklo);
    cudaGetSymbolAddress((void**)&wvhi, g_wvhi); cudaGetSymbolAddress((void**)&wvlo, g_wvlo);
    cudaGetSymbolAddress((void**)&wohi, g_wohi); cudaGetSymbolAddress((void**)&wolo, g_wolo);
    cudaGetSymbolAddress((void**)&qhi, g_qhi);   cudaGetSymbolAddress((void**)&qlo, g_qlo);
    cudaGetSymbolAddress((void**)&khi, g_khi);   cudaGetSymbolAddress((void**)&klo, g_klo);
    cudaGetSymbolAddress((void**)&vhi, g_vhi);   cudaGetSymbolAddress((void**)&vlo, g_vlo);
    cudaGetSymbolAddress((void**)&chi, g_chi);   cudaGetSymbolAddress((void**)&clo, g_clo);

    const int nx4 = MROWS * DM / 4;
    const int nw4 = DM * DM / 4;
    split_kernel<<<(nx4 + 255) / 256, 256>>>(x,  xhi,  xlo,  nx4, 1.0f);
    split_kernel<<<(nw4 + 255) / 256, 256>>>(Wq, wqhi, wqlo, nw4, 0.125f);  // fold 1/sqrt(dk)
    split_kernel<<<(nw4 + 255) / 256, 256>>>(Wk, wkhi, wklo, nw4, 1.0f);
    split_kernel<<<(nw4 + 255) / 256, 256>>>(Wv, wvhi, wvlo, nw4, 1.0f);
    split_kernel<<<(nw4 + 255) / 256, 256>>>(Wo, wohi, wolo, nw4, 1.0f);

    cudaFuncSetAttribute(gemm_tc, cudaFuncAttributeMaxDynamicSharedMemorySize, GEMM_SMEM);
    cudaFuncSetAttribute(attn_tc, cudaFuncAttributeMaxDynamicSharedMemorySize, ATT_SMEM);

    const dim3 ggrid(DM / 128, MROWS / 128);   // (8, 32)
    gemm_tc<<<ggrid, 256, GEMM_SMEM>>>(xhi, xlo, wqhi, wqlo, nullptr, qhi, qlo, 1);
    gemm_tc<<<ggrid, 256, GEMM_SMEM>>>(xhi, xlo, wkhi, wklo, nullptr, khi, klo, 1);
    gemm_tc<<<ggrid, 256, GEMM_SMEM>>>(xhi, xlo, wvhi, wvlo, nullptr, vhi, vlo, 1);

    attn_tc<<<dim3(LL / 128, BB * HH), 256, ATT_SMEM>>>(
        qhi, qlo, khi, klo, vhi, vlo, bias, mask, chi, clo);

    gemm_tc<<<ggrid, 256, GEMM_SMEM>>>(chi, clo, wohi, wolo, out, nullptr, nullptr, 0);
}

// round 12
// speedup vs baseline: 1.2165x; 1.2165x over previous
#include <cuda_runtime.h>
#include <cuda_bf16.h>
#include <cuda_fp16.h>
#include <math.h>
#include <cstdint>

#define BB   2
#define LL   2048
#define DM   1024
#define HH   16
#define DKK  64
#define MROWS (BB*LL)

typedef __nv_bfloat16 bf16;

// ---------------- scratch ----------------
__device__ bf16 g_xhi[(size_t)MROWS*DM];
__device__ bf16 g_xlo[(size_t)MROWS*DM];
__device__ bf16 g_wqhi[(size_t)DM*DM];
__device__ bf16 g_wqlo[(size_t)DM*DM];
__device__ bf16 g_wkhi[(size_t)DM*DM];
__device__ bf16 g_wklo[(size_t)DM*DM];
__device__ bf16 g_wvhi[(size_t)DM*DM];
__device__ bf16 g_wvlo[(size_t)DM*DM];
__device__ bf16 g_wohi[(size_t)DM*DM];
__device__ bf16 g_wolo[(size_t)DM*DM];
__device__ __half g_qhf[(size_t)BB*HH*LL*DKK];
__device__ __half g_qlf[(size_t)BB*HH*LL*DKK];
__device__ __half g_khf[(size_t)BB*HH*LL*DKK];
__device__ __half g_vhf[(size_t)BB*HH*LL*DKK];
__device__ bf16 g_chi[(size_t)MROWS*DM];
__device__ bf16 g_clo[(size_t)MROWS*DM];

// ---------------- helpers ----------------
__device__ __forceinline__ uint32_t smem_u32(const void* p) {
    uint32_t a;
    asm("{ .reg .u64 t; cvta.to.shared.u64 t, %1; cvt.u32.u64 %0, t; }" : "=r"(a) : "l"(p));
    return a;
}
__device__ __forceinline__ void ldsm4(uint32_t* r, uint32_t a) {
    asm volatile("ldmatrix.sync.aligned.m8n8.x4.shared.b16 {%0,%1,%2,%3}, [%4];"
        : "=r"(r[0]), "=r"(r[1]), "=r"(r[2]), "=r"(r[3]) : "r"(a));
}
__device__ __forceinline__ void ldsm4t(uint32_t* r, uint32_t a) {
    asm volatile("ldmatrix.sync.aligned.m8n8.x4.trans.shared.b16 {%0,%1,%2,%3}, [%4];"
        : "=r"(r[0]), "=r"(r[1]), "=r"(r[2]), "=r"(r[3]) : "r"(a));
}
// bf16 mma
__device__ __forceinline__ void mma_bf(float* c, const uint32_t* a, uint32_t b0, uint32_t b1) {
    asm volatile(
        "mma.sync.aligned.m16n8k16.row.col.f32.bf16.bf16.f32 "
        "{%0,%1,%2,%3}, {%4,%5,%6,%7}, {%8,%9}, {%0,%1,%2,%3};"
        : "+f"(c[0]), "+f"(c[1]), "+f"(c[2]), "+f"(c[3])
        : "r"(a[0]), "r"(a[1]), "r"(a[2]), "r"(a[3]), "r"(b0), "r"(b1));
}
// fp16 mma
__device__ __forceinline__ void mma_f16(float* c, const uint32_t* a, uint32_t b0, uint32_t b1) {
    asm volatile(
        "mma.sync.aligned.m16n8k16.row.col.f32.f16.f16.f32 "
        "{%0,%1,%2,%3}, {%4,%5,%6,%7}, {%8,%9}, {%0,%1,%2,%3};"
        : "+f"(c[0]), "+f"(c[1]), "+f"(c[2]), "+f"(c[3])
        : "r"(a[0]), "r"(a[1]), "r"(a[2]), "r"(a[3]), "r"(b0), "r"(b1));
}
__device__ __forceinline__ void cp16(uint32_t dst, const void* src) {
    asm volatile("cp.async.cg.shared.global [%0], [%1], 16;" :: "r"(dst), "l"(src));
}
#define CP_COMMIT() asm volatile("cp.async.commit_group;" ::: "memory")
#define CP_WAIT0()  asm volatile("cp.async.wait_group 0;" ::: "memory")

__device__ __forceinline__ uint32_t pack_h2(__half a, __half b) {
    __half2 t{a, b};
    return *reinterpret_cast<uint32_t*>(&t);
}
__device__ __forceinline__ void store_hilo_bf(bf16* Hi, bf16* Lo, size_t idx, float x, float y) {
    bf16 hx = __float2bfloat16(x), hy = __float2bfloat16(y);
    __nv_bfloat162 hp{hx, hy};
    *reinterpret_cast<__nv_bfloat162*>(&Hi[idx]) = hp;
    __nv_bfloat162 lp{__float2bfloat16(x - __bfloat162float(hx)),
                      __float2bfloat16(y - __bfloat162float(hy))};
    *reinterpret_cast<__nv_bfloat162*>(&Lo[idx]) = lp;
}
__device__ __forceinline__ void store_hilo_f16(__half* Hi, __half* Lo, size_t idx, float x, float y) {
    __half hx = __float2half(x), hy = __float2half(y);
    __half2 hp{hx, hy};
    *reinterpret_cast<__half2*>(&Hi[idx]) = hp;
    __half2 lp{__float2half(x - __half2float(hx)),
               __float2half(y - __half2float(hy))};
    *reinterpret_cast<__half2*>(&Lo[idx]) = lp;
}

extern __shared__ char dynsmem[];

// ---------------------------------------------------------------------------
// split: fp32 -> (scale*) bf16 hi + bf16 lo
// ---------------------------------------------------------------------------
__global__ __launch_bounds__(256) void split_kernel(
    const float* __restrict__ in, bf16* __restrict__ hi, bf16* __restrict__ lo,
    int n4, float scale)
{
    int i = blockIdx.x * blockDim.x + threadIdx.x;
    if (i >= n4) return;
    float4 v = ((const float4*)in)[i];
    v.x *= scale; v.y *= scale; v.z *= scale; v.w *= scale;
    bf16 h0 = __float2bfloat16(v.x), h1 = __float2bfloat16(v.y);
    bf16 h2 = __float2bfloat16(v.z), h3 = __float2bfloat16(v.w);
    ((__nv_bfloat162*)hi)[2*i]   = {h0, h1};
    ((__nv_bfloat162*)hi)[2*i+1] = {h2, h3};
    ((__nv_bfloat162*)lo)[2*i]   = {__float2bfloat16(v.x - __bfloat162float(h0)),
                                    __float2bfloat16(v.y - __bfloat162float(h1))};
    ((__nv_bfloat162*)lo)[2*i+1] = {__float2bfloat16(v.z - __bfloat162float(h2)),
                                    __float2bfloat16(v.w - __bfloat162float(h3))};
}

// ---------------------------------------------------------------------------
// HMMA bf16-split NT GEMM, cp.async 2-stage pipeline, K-chunk 32.
// Block 128x128, 8 warps (2M x 4N). 3 products, fp32 accum.
// mode 0: fp32 row-major; mode 1: fp16 hi/lo head layout (Q);
// mode 2: fp16 single-plane head layout (K, V).
// ---------------------------------------------------------------------------
#define GP 80
#define G_PLANE (128*GP)
#define G_STAGE (4*G_PLANE)
#define GEMM_SMEM (2*G_STAGE)       // 81920 B

__global__ __launch_bounds__(256, 2) void gemm_tc(
    const bf16* __restrict__ Ahi, const bf16* __restrict__ Alo,
    const bf16* __restrict__ Whi, const bf16* __restrict__ Wlo,
    float* __restrict__ Cf, __half* __restrict__ Hh, __half* __restrict__ Hl,
    int mode)
{
    const uint32_t smb = smem_u32(dynsmem);
    const int tid = threadIdx.x, lane = tid & 31, wid = tid >> 5;
    const int wm = wid >> 2, wn = wid & 3;
    const int m0 = blockIdx.y * 128, n0 = blockIdx.x * 128;
    const int r0 = lane >> 2, cq = (lane & 3) * 2;

    const bf16* plane_src[4] = {Ahi, Alo, Whi, Wlo};
    const int   plane_row0[4] = {m0, m0, n0, n0};

    auto issue_chunk = [&](int kc) {
        const uint32_t sbase = smb + (kc & 1) * G_STAGE;
        #pragma unroll
        for (int it = 0; it < 8; it++) {
            const int idx = tid + it * 256;
            const int pl  = idx >> 9;
            const int r   = (idx >> 2) & 127;
            const int seg = idx & 3;
            cp16(sbase + pl * G_PLANE + r * GP + seg * 16,
                 plane_src[pl] + (size_t)(plane_row0[pl] + r) * DM + kc * 32 + seg * 8);
        }
    };

    float acc[4][4][4];
    #pragma unroll
    for (int i = 0; i < 4; i++)
        #pragma unroll
        for (int j = 0; j < 4; j++)
            #pragma unroll
            for (int q = 0; q < 4; q++) acc[i][j][q] = 0.f;

    issue_chunk(0);
    CP_COMMIT();

    for (int kc = 0; kc < 32; kc++) {
        CP_WAIT0();
        __syncthreads();
        if (kc + 1 < 32) { issue_chunk(kc + 1); CP_COMMIT(); }

        const uint32_t sbase = smb + (kc & 1) * G_STAGE;
        #pragma unroll
        for (int t = 0; t < 2; t++) {
            const uint32_t qoff = (lane & 15) * GP + (lane >> 4) * 16 + t * 32;
            uint32_t ah[4][4], al[4][4];
            #pragma unroll
            for (int mf = 0; mf < 4; mf++) {
                const uint32_t ra = (wm*64 + mf*16) * GP + qoff;
                ldsm4(ah[mf], sbase + 0*G_PLANE + ra);
                ldsm4(al[mf], sbase + 1*G_PLANE + ra);
            }
            #pragma unroll
            for (int jp = 0; jp < 2; jp++) {
                const uint32_t rb = (wn*32 + jp*16) * GP + qoff;
                uint32_t bh[4], bl[4];
                ldsm4(bh, sbase + 2*G_PLANE + rb);
                ldsm4(bl, sbase + 3*G_PLANE + rb);
                #pragma unroll
                for (int mf = 0; mf < 4; mf++) {
                    mma_bf(acc[mf][2*jp],   ah[mf], bh[0], bh[2]);
                    mma_bf(acc[mf][2*jp+1], ah[mf], bh[1], bh[3]);
                    mma_bf(acc[mf][2*jp],   ah[mf], bl[0], bl[2]);
                    mma_bf(acc[mf][2*jp+1], ah[mf], bl[1], bl[3]);
                    mma_bf(acc[mf][2*jp],   al[mf], bh[0], bh[2]);
                    mma_bf(acc[mf][2*jp+1], al[mf], bh[1], bh[3]);
                }
            }
        }
    }

    #pragma unroll
    for (int mf = 0; mf < 4; mf++) {
        const int mr = m0 + wm*64 + mf*16 + r0;
        #pragma unroll
        for (int jf = 0; jf < 4; jf++) {
            const int col = n0 + wn*32 + jf*8 + cq;
            if (mode == 0) {
                *(float2*)&Cf[(size_t)mr * DM + col] =
                    make_float2(acc[mf][jf][0], acc[mf][jf][1]);
                *(float2*)&Cf[(size_t)(mr+8) * DM + col] =
                    make_float2(acc[mf][jf][2], acc[mf][jf][3]);
            } else {
                const int h = col >> 6, d = col & 63;
                const int b0_ = mr >> 11, l0 = mr & 2047;
                const size_t i0 = (((size_t)(b0_*HH + h) * LL + l0) * DKK + d);
                const int mr1 = mr + 8;
                const int b1_ = mr1 >> 11, l1 = mr1 & 2047;
                const size_t i1 = (((size_t)(b1_*HH + h) * LL + l1) * DKK + d);
                if (mode == 1) {
                    store_hilo_f16(Hh, Hl, i0, acc[mf][jf][0], acc[mf][jf][1]);
                    store_hilo_f16(Hh, Hl, i1, acc[mf][jf][2], acc[mf][jf][3]);
                } else {
                    *(__half2*)&Hh[i0] = __half2{__float2half(acc[mf][jf][0]),
                                                 __float2half(acc[mf][jf][1])};
                    *(__half2*)&Hh[i1] = __half2{__float2half(acc[mf][jf][2]),
                                                 __float2half(acc[mf][jf][3])};
                }
            }
        }
    }
}

// ---------------------------------------------------------------------------
// HMMA fp16 flash attention: Q 2-plane fp16 x K 1-plane fp16 (2 chains),
// P 2-plane fp16 x V 1-plane fp16 (2 chains). cp.async 2-stage KV pipeline.
// Q pre-scaled by 1/sqrt(dk) (folded into Wq). Bias+mask preload into sacc.
// Grid (L/128, B*H), 8 warps; warp = 16 q-rows x 64-key tile.
// ---------------------------------------------------------------------------
#define AP 144
#define AQ_PLANE (128*AP)           // 18432 B
#define AKV_PLANE (64*AP)           // 9216 B
#define AKV_STAGE (2*AKV_PLANE)     // 18432 B (K + V, single plane each)
#define ATT_SMEM (2*AQ_PLANE + 2*AKV_STAGE)  // 73728 B -> 2 CTAs/SM

__global__ __launch_bounds__(256, 2) void attn_tc(
    const __half* __restrict__ Qh, const __half* __restrict__ Ql,
    const __half* __restrict__ Kh, const __half* __restrict__ Vh,
    const float* __restrict__ bias, const float* __restrict__ mask,
    bf16* __restrict__ Chi, bf16* __restrict__ Clo)
{
    const uint32_t smb = smem_u32(dynsmem);
    const int tid = threadIdx.x, lane = tid & 31, wid = tid >> 5;
    const int bh = blockIdx.y;
    const int b  = bh >> 4, h = bh & 15;
    const int q0 = blockIdx.x * 128;
    const int wr = wid * 16;
    const int r0 = lane >> 2, cq = (lane & 3) * 2;

    const __half* Qpl[2] = {Qh + (size_t)bh * LL * DKK, Ql + (size_t)bh * LL * DKK};
    const __half* KVpl[2] = {Kh + (size_t)bh * LL * DKK, Vh + (size_t)bh * LL * DKK};
    const float* brow0 = bias + ((size_t)bh * LL + (q0 + wr + r0)) * LL;
    const float* brow1 = brow0 + 8 * (size_t)LL;
    const float* maskb = mask + (size_t)b * LL;

    // one KV tile = 2 planes x 64 rows x 8 segs(16B) = 1024 cp16
    auto issue_kv = [&](int kt) {
        const uint32_t sbase = smb + 2*AQ_PLANE + (kt & 1) * AKV_STAGE;
        const int k0 = kt * 64;
        #pragma unroll
        for (int it = 0; it < 4; it++) {
            const int idx = tid + it * 256;       // 0..1023
            const int pl  = idx >> 9;
            const int r   = (idx >> 3) & 63;
            const int seg = idx & 7;
            cp16(sbase + pl * AKV_PLANE + r * AP + seg * 16,
                 KVpl[pl] + (size_t)(k0 + r) * DKK + seg * 8);
        }
    };

    // prologue: Q (2 planes x 128 rows x 8 segs = 2048) + KV tile 0
    #pragma unroll
    for (int it = 0; it < 8; it++) {
        const int idx = tid + it * 256;
        const int pl  = idx >> 10;
        const int r   = (idx >> 3) & 127;
        const int seg = idx & 7;
        cp16(smb + pl * AQ_PLANE + r * AP + seg * 16,
             Qpl[pl] + (size_t)(q0 + r) * DKK + seg * 8);
    }
    issue_kv(0);
    CP_COMMIT();

    float m_i[2] = {-1e30f, -1e30f}, l_i[2] = {0.f, 0.f};
    float oacc[8][4];
    #pragma unroll
    for (int j = 0; j < 8; j++)
        #pragma unroll
        for (int q = 0; q < 4; q++) oacc[j][q] = 0.f;

    for (int kt = 0; kt < LL/64; kt++) {
        const int k0 = kt * 64;
        CP_WAIT0();
        __syncthreads();
        if (kt + 1 < LL/64) { issue_kv(kt + 1); CP_COMMIT(); }

        const uint32_t kvK = smb + 2*AQ_PLANE + (kt & 1) * AKV_STAGE;
        const uint32_t kvV = kvK + AKV_PLANE;

        // ---- S init = bias + mask ----
        float sacc[8][4];
        #pragma unroll
        for (int j = 0; j < 8; j++) {
            const int kc = k0 + j*8 + cq;
            float2 bz0 = *(const float2*)&brow0[kc];
            float2 bz1 = *(const float2*)&brow1[kc];
            float2 mz  = *(const float2*)&maskb[kc];
            sacc[j][0] = bz0.x + mz.x;
            sacc[j][1] = bz0.y + mz.y;
            sacc[j][2] = bz1.x + mz.x;
            sacc[j][3] = bz1.y + mz.y;
        }

        // ---- S += (Qhi + Qlo) K^T  (2 chains) ----
        #pragma unroll
        for (int t = 0; t < 4; t++) {
            const uint32_t qoff = (lane & 15) * AP + (lane >> 4) * 16 + t * 32;
            uint32_t qa[4], ql[4];
            ldsm4(qa, smb + 0*AQ_PLANE + wr * AP + qoff);
            ldsm4(ql, smb + 1*AQ_PLANE + wr * AP + qoff);
            #pragma unroll
            for (int jp = 0; jp < 4; jp++) {
                uint32_t kb[4];
                ldsm4(kb, kvK + (jp*16) * AP + qoff);
                mma_f16(sacc[2*jp],   qa, kb[0], kb[2]);
                mma_f16(sacc[2*jp+1], qa, kb[1], kb[3]);
                mma_f16(sacc[2*jp],   ql, kb[0], kb[2]);
                mma_f16(sacc[2*jp+1], ql, kb[1], kb[3]);
            }
        }

        // ---- row max ----
        float mx0 = -1e30f, mx1 = -1e30f;
        #pragma unroll
        for (int j = 0; j < 8; j++) {
            mx0 = fmaxf(mx0, fmaxf(sacc[j][0], sacc[j][1]));
            mx1 = fmaxf(mx1, fmaxf(sacc[j][2], sacc[j][3]));
        }
        mx0 = fmaxf(mx0, __shfl_xor_sync(0xffffffffu, mx0, 1));
        mx0 = fmaxf(mx0, __shfl_xor_sync(0xffffffffu, mx0, 2));
        mx1 = fmaxf(mx1, __shfl_xor_sync(0xffffffffu, mx1, 1));
        mx1 = fmaxf(mx1, __shfl_xor_sync(0xffffffffu, mx1, 2));

        const float mn0 = fmaxf(m_i[0], mx0);
        const float mn1 = fmaxf(m_i[1], mx1);
        const float corr0 = __expf(m_i[0] - mn0);
        const float corr1 = __expf(m_i[1] - mn1);
        m_i[0] = mn0; m_i[1] = mn1;

        // ---- exp + split P into fp16 hi/lo ----
        uint32_t ph[4][4], pl[4][4];
        float rs0 = 0.f, rs1 = 0.f;
        #pragma unroll
        for (int j = 0; j < 8; j++) {
            float p0 = __expf(sacc[j][0] - mn0);
            float p1 = __expf(sacc[j][1] - mn0);
            float p2 = __expf(sacc[j][2] - mn1);
            float p3 = __expf(sacc[j][3] - mn1);
            rs0 += p0 + p1; rs1 += p2 + p3;
            __half h0 = __float2half(p0), h1 = __float2half(p1);
            __half h2 = __float2half(p2), h3 = __float2half(p3);
            const int t = j >> 1, s = (j & 1) * 2;
            ph[t][s+0] = pack_h2(h0, h1);
            ph[t][s+1] = pack_h2(h2, h3);
            pl[t][s+0] = pack_h2(__float2half(p0 - __half2float(h0)),
                                 __float2half(p1 - __half2float(h1)));
            pl[t][s+1] = pack_h2(__float2half(p2 - __half2float(h2)),
                                 __float2half(p3 - __half2float(h3)));
        }
        rs0 += __shfl_xor_sync(0xffffffffu, rs0, 1);
        rs0 += __shfl_xor_sync(0xffffffffu, rs0, 2);
        rs1 += __shfl_xor_sync(0xffffffffu, rs1, 1);
        rs1 += __shfl_xor_sync(0xffffffffu, rs1, 2);
        l_i[0] = l_i[0] * corr0 + rs0;
        l_i[1] = l_i[1] * corr1 + rs1;

        #pragma unroll
        for (int j = 0; j < 8; j++) {
            oacc[j][0] *= corr0; oacc[j][1] *= corr0;
            oacc[j][2] *= corr1; oacc[j][3] *= corr1;
        }

        // ---- O += (Phi + Plo) V  (2 chains) ----
        #pragma unroll
        for (int j = 0; j < 8; j++) {
            #pragma unroll
            for (int tp = 0; tp < 2; tp++) {
                const uint32_t va = (tp*32 + lane) * AP + j * 16;
                uint32_t vh[4];
                ldsm4t(vh, kvV + va);
                mma_f16(oacc[j], ph[2*tp],   vh[0], vh[1]);
                mma_f16(oacc[j], pl[2*tp],   vh[0], vh[1]);
                mma_f16(oacc[j], ph[2*tp+1], vh[2], vh[3]);
                mma_f16(oacc[j], pl[2*tp+1], vh[2], vh[3]);
            }
        }
    }

    // ---- epilogue: ctx bf16 hi/lo planes, (B*L, DM) layout ----
    const float inv0 = 1.0f / l_i[0];
    const float inv1 = 1.0f / l_i[1];
    const size_t row0 = (size_t)(b * LL + q0 + wr + r0);
    const size_t row1 = row0 + 8;
    #pragma unroll
    for (int j = 0; j < 8; j++) {
        const int col = h * DKK + j * 8 + cq;
        store_hilo_bf(Chi, Clo, row0 * DM + col, oacc[j][0] * inv0, oacc[j][1] * inv0);
        store_hilo_bf(Chi, Clo, row1 * DM + col, oacc[j][2] * inv1, oacc[j][3] * inv1);
    }
}

// ---------------------------------------------------------------------------
extern "C" void kernel_launch(void* const* d_in, const int* in_sizes, int n_in,
                              void* d_out, int out_size)
{
    const float* x    = (const float*)d_in[0];
    const float* Wq   = (const float*)d_in[1];
    const float* Wk   = (const float*)d_in[2];
    const float* Wv   = (const float*)d_in[3];
    const float* Wo   = (const float*)d_in[4];
    const float* bias = (const float*)d_in[5];
    const float* mask = (const float*)d_in[6];
    float* out = (float*)d_out;

    bf16 *xhi, *xlo, *wqhi, *wqlo, *wkhi, *wklo, *wvhi, *wvlo, *wohi, *wolo, *chi, *clo;
    __half *qhf, *qlf, *khf, *vhf;
    cudaGetSymbolAddress((void**)&xhi, g_xhi);   cudaGetSymbolAddress((void**)&xlo, g_xlo);
    cudaGetSymbolAddress((void**)&wqhi, g_wqhi); cudaGetSymbolAddress((void**)&wqlo, g_wqlo);
    cudaGetSymbolAddress((void**)&wkhi, g_wkhi); cudaGetSymbolAddress((void**)&wklo, g_wklo);
    cudaGetSymbolAddress((void**)&wvhi, g_wvhi); cudaGetSymbolAddress((void**)&wvlo, g_wvlo);
    cudaGetSymbolAddress((void**)&wohi, g_wohi); cudaGetSymbolAddress((void**)&wolo, g_wolo);
    cudaGetSymbolAddress((void**)&qhf, g_qhf);   cudaGetSymbolAddress((void**)&qlf, g_qlf);
    cudaGetSymbolAddress((void**)&khf, g_khf);   cudaGetSymbolAddress((void**)&vhf, g_vhf);
    cudaGetSymbolAddress((void**)&chi, g_chi);   cudaGetSymbolAddress((void**)&clo, g_clo);

    const int nx4 = MROWS * DM / 4;
    const int nw4 = DM * DM / 4;
    split_kernel<<<(nx4 + 255) / 256, 256>>>(x,  xhi,  xlo,  nx4, 1.0f);
    split_kernel<<<(nw4 + 255) / 256, 256>>>(Wq, wqhi, wqlo, nw4, 0.125f);  // fold 1/sqrt(dk)
    split_kernel<<<(nw4 + 255) / 256, 256>>>(Wk, wkhi, wklo, nw4, 1.0f);
    split_kernel<<<(nw4 + 255) / 256, 256>>>(Wv, wvhi, wvlo, nw4, 1.0f);
    split_kernel<<<(nw4 + 255) / 256, 256>>>(Wo, wohi, wolo, nw4, 1.0f);

    cudaFuncSetAttribute(gemm_tc, cudaFuncAttributeMaxDynamicSharedMemorySize, GEMM_SMEM);
    cudaFuncSetAttribute(attn_tc, cudaFuncAttributeMaxDynamicSharedMemorySize, ATT_SMEM);

    const dim3 ggrid(DM / 128, MROWS / 128);   // (8, 32)
    gemm_tc<<<ggrid, 256, GEMM_SMEM>>>(xhi, xlo, wqhi, wqlo, nullptr, qhf, qlf, 1);
    gemm_tc<<<ggrid, 256, GEMM_SMEM>>>(xhi, xlo, wkhi, wklo, nullptr, khf, nullptr, 2);
    gemm_tc<<<ggrid, 256, GEMM_SMEM>>>(xhi, xlo, wvhi, wvlo, nullptr, vhf, nullptr, 2);

    attn_tc<<<dim3(LL / 128, BB * HH), 256, ATT_SMEM>>>(
        qhf, qlf, khf, vhf, bias, mask, chi, clo);

    gemm_tc<<<ggrid, 256, GEMM_SMEM>>>(chi, clo, wohi, wolo, out, nullptr, nullptr, 0);
}

// round 14
// speedup vs baseline: 1.7600x; 1.4468x over previous
#include <cuda_runtime.h>
#include <cuda_bf16.h>
#include <cuda_fp16.h>
#include <math.h>
#include <cstdint>

#define BB   2
#define LL   2048
#define DM   1024
#define HH   16
#define DKK  64
#define MROWS (BB*LL)

// ---------------- scratch ----------------
__device__ __half g_xhi[(size_t)MROWS*DM];
__device__ __half g_xlo[(size_t)MROWS*DM];
__device__ __half g_wq[(size_t)DM*DM];
__device__ __half g_wk[(size_t)DM*DM];
__device__ __half g_wv[(size_t)DM*DM];
__device__ __half g_wo[(size_t)DM*DM];
__device__ __half g_qhf[(size_t)BB*HH*LL*DKK];
__device__ __half g_khf[(size_t)BB*HH*LL*DKK];
__device__ __half g_vhf[(size_t)BB*HH*LL*DKK];
__device__ __half g_chi[(size_t)MROWS*DM];
__device__ __half g_clo[(size_t)MROWS*DM];

// ---------------- helpers ----------------
__device__ __forceinline__ uint32_t smem_u32(const void* p) {
    uint32_t a;
    asm("{ .reg .u64 t; cvta.to.shared.u64 t, %1; cvt.u32.u64 %0, t; }" : "=r"(a) : "l"(p));
    return a;
}
__device__ __forceinline__ void ldsm4(uint32_t* r, uint32_t a) {
    asm volatile("ldmatrix.sync.aligned.m8n8.x4.shared.b16 {%0,%1,%2,%3}, [%4];"
        : "=r"(r[0]), "=r"(r[1]), "=r"(r[2]), "=r"(r[3]) : "r"(a));
}
__device__ __forceinline__ void ldsm4t(uint32_t* r, uint32_t a) {
    asm volatile("ldmatrix.sync.aligned.m8n8.x4.trans.shared.b16 {%0,%1,%2,%3}, [%4];"
        : "=r"(r[0]), "=r"(r[1]), "=r"(r[2]), "=r"(r[3]) : "r"(a));
}
__device__ __forceinline__ void mma_f16(float* c, const uint32_t* a, uint32_t b0, uint32_t b1) {
    asm volatile(
        "mma.sync.aligned.m16n8k16.row.col.f32.f16.f16.f32 "
        "{%0,%1,%2,%3}, {%4,%5,%6,%7}, {%8,%9}, {%0,%1,%2,%3};"
        : "+f"(c[0]), "+f"(c[1]), "+f"(c[2]), "+f"(c[3])
        : "r"(a[0]), "r"(a[1]), "r"(a[2]), "r"(a[3]), "r"(b0), "r"(b1));
}
__device__ __forceinline__ void cp16(uint32_t dst, const void* src) {
    asm volatile("cp.async.cg.shared.global [%0], [%1], 16;" :: "r"(dst), "l"(src));
}
#define CP_COMMIT() asm volatile("cp.async.commit_group;" ::: "memory")
#define CP_WAIT0()  asm volatile("cp.async.wait_group 0;" ::: "memory")

__device__ __forceinline__ uint32_t pack_h2(__half a, __half b) {
    __half2 t{a, b};
    return *reinterpret_cast<uint32_t*>(&t);
}
__device__ __forceinline__ void store_hilo_f16(__half* Hi, __half* Lo, size_t idx, float x, float y) {
    __half hx = __float2half(x), hy = __float2half(y);
    __half2 hp{hx, hy};
    *reinterpret_cast<__half2*>(&Hi[idx]) = hp;
    __half2 lp{__float2half(x - __half2float(hx)),
               __float2half(y - __half2float(hy))};
    *reinterpret_cast<__half2*>(&Lo[idx]) = lp;
}

extern __shared__ char dynsmem[];

// ---------------------------------------------------------------------------
// split: fp32 -> fp16 hi + fp16 lo (exact pair to ~2^-22)
// ---------------------------------------------------------------------------
__global__ __launch_bounds__(256) void split_f16(
    const float* __restrict__ in, __half* __restrict__ hi, __half* __restrict__ lo, int n4)
{
    int i = blockIdx.x * blockDim.x + threadIdx.x;
    if (i >= n4) return;
    float4 v = ((const float4*)in)[i];
    __half h0 = __float2half(v.x), h1 = __float2half(v.y);
    __half h2 = __float2half(v.z), h3 = __float2half(v.w);
    ((__half2*)hi)[2*i]   = {h0, h1};
    ((__half2*)hi)[2*i+1] = {h2, h3};
    ((__half2*)lo)[2*i]   = {__float2half(v.x - __half2float(h0)),
                             __float2half(v.y - __half2float(h1))};
    ((__half2*)lo)[2*i+1] = {__float2half(v.z - __half2float(h2)),
                             __float2half(v.w - __half2float(h3))};
}

// conv: fp32 -> (scale*) fp16 single plane
__global__ __launch_bounds__(256) void conv_f16(
    const float* __restrict__ in, __half* __restrict__ out, int n4, float scale)
{
    int i = blockIdx.x * blockDim.x + threadIdx.x;
    if (i >= n4) return;
    float4 v = ((const float4*)in)[i];
    ((__half2*)out)[2*i]   = {__float2half(v.x * scale), __float2half(v.y * scale)};
    ((__half2*)out)[2*i+1] = {__float2half(v.z * scale), __float2half(v.w * scale)};
}

// ---------------------------------------------------------------------------
// HMMA fp16 asymmetric NT GEMM: C = (Ahi + Alo) @ W^T, 2 chains, fp32 accum.
// cp.async 2-stage, K-chunk 32. Block 128x128, 8 warps (2M x 4N).
// mode 0: fp32 row-major out; mode 2: fp16 single-plane head layout out.
// ---------------------------------------------------------------------------
#define GP 80
#define G_PLANE (128*GP)            // 10240 B
#define G_STAGE (3*G_PLANE)         // 30720 B (Ahi, Alo, W)
#define GEMM_SMEM (2*G_STAGE)       // 61440 B

__global__ __launch_bounds__(256, 2) void gemm_tc(
    const __half* __restrict__ Ahi, const __half* __restrict__ Alo,
    const __half* __restrict__ W,
    float* __restrict__ Cf, __half* __restrict__ Hf, int mode)
{
    const uint32_t smb = smem_u32(dynsmem);
    const int tid = threadIdx.x, lane = tid & 31, wid = tid >> 5;
    const int wm = wid >> 2, wn = wid & 3;
    const int m0 = blockIdx.y * 128, n0 = blockIdx.x * 128;
    const int r0 = lane >> 2, cq = (lane & 3) * 2;

    const __half* plane_src[3] = {Ahi, Alo, W};
    const int   plane_row0[3] = {m0, m0, n0};

    // one chunk = 3 planes x 128 rows x 4 segs(16B) = 1536 cp16
    auto issue_chunk = [&](int kc) {
        const uint32_t sbase = smb + (kc & 1) * G_STAGE;
        #pragma unroll
        for (int it = 0; it < 6; it++) {
            const int idx = tid + it * 256;        // 0..1535
            const int pl  = idx >> 9;
            const int r   = (idx >> 2) & 127;
            const int seg = idx & 3;
            cp16(sbase + pl * G_PLANE + r * GP + seg * 16,
                 plane_src[pl] + (size_t)(plane_row0[pl] + r) * DM + kc * 32 + seg * 8);
        }
    };

    float acc[4][4][4];
    #pragma unroll
    for (int i = 0; i < 4; i++)
        #pragma unroll
        for (int j = 0; j < 4; j++)
            #pragma unroll
            for (int q = 0; q < 4; q++) acc[i][j][q] = 0.f;

    issue_chunk(0);
    CP_COMMIT();

    for (int kc = 0; kc < 32; kc++) {
        CP_WAIT0();
        __syncthreads();
        if (kc + 1 < 32) { issue_chunk(kc + 1); CP_COMMIT(); }

        const uint32_t sbase = smb + (kc & 1) * G_STAGE;
        #pragma unroll
        for (int t = 0; t < 2; t++) {
            const uint32_t qoff = (lane & 15) * GP + (lane >> 4) * 16 + t * 32;
            uint32_t ah[4][4], al[4][4];
            #pragma unroll
            for (int mf = 0; mf < 4; mf++) {
                const uint32_t ra = (wm*64 + mf*16) * GP + qoff;
                ldsm4(ah[mf], sbase + 0*G_PLANE + ra);
                ldsm4(al[mf], sbase + 1*G_PLANE + ra);
            }
            #pragma unroll
            for (int jp = 0; jp < 2; jp++) {
                const uint32_t rb = (wn*32 + jp*16) * GP + qoff;
                uint32_t bh[4];
                ldsm4(bh, sbase + 2*G_PLANE + rb);
                #pragma unroll
                for (int mf = 0; mf < 4; mf++) {
                    mma_f16(acc[mf][2*jp],   ah[mf], bh[0], bh[2]);
                    mma_f16(acc[mf][2*jp+1], ah[mf], bh[1], bh[3]);
                    mma_f16(acc[mf][2*jp],   al[mf], bh[0], bh[2]);
                    mma_f16(acc[mf][2*jp+1], al[mf], bh[1], bh[3]);
                }
            }
        }
    }

    #pragma unroll
    for (int mf = 0; mf < 4; mf++) {
        const int mr = m0 + wm*64 + mf*16 + r0;
        #pragma unroll
        for (int jf = 0; jf < 4; jf++) {
            const int col = n0 + wn*32 + jf*8 + cq;
            if (mode == 0) {
                *(float2*)&Cf[(size_t)mr * DM + col] =
                    make_float2(acc[mf][jf][0], acc[mf][jf][1]);
                *(float2*)&Cf[(size_t)(mr+8) * DM + col] =
                    make_float2(acc[mf][jf][2], acc[mf][jf][3]);
            } else {
                const int h = col >> 6, d = col & 63;
                const int b0_ = mr >> 11, l0 = mr & 2047;
                const size_t i0 = (((size_t)(b0_*HH + h) * LL + l0) * DKK + d);
                const int mr1 = mr + 8;
                const int b1_ = mr1 >> 11, l1 = mr1 & 2047;
                const size_t i1 = (((size_t)(b1_*HH + h) * LL + l1) * DKK + d);
                *(__half2*)&Hf[i0] = __half2{__float2half(acc[mf][jf][0]),
                                             __float2half(acc[mf][jf][1])};
                *(__half2*)&Hf[i1] = __half2{__float2half(acc[mf][jf][2]),
                                             __float2half(acc[mf][jf][3])};
            }
        }
    }
}

// ---------------------------------------------------------------------------
// HMMA fp16 flash attention, single-plane Q/K/P/V (1+1 chains).
// Q pre-scaled by 1/sqrt(dk) (folded into Wq). Bias+mask preload into sacc.
// Normalization uses the ROUNDED P so rounding partially cancels in the ratio.
// Grid (L/128, B*H), 8 warps; warp = 16 q-rows x 64-key tile.
// ---------------------------------------------------------------------------
#define AP 144
#define AQ_PLANE (128*AP)           // 18432 B
#define AKV_PLANE (64*AP)           // 9216 B
#define AKV_STAGE (2*AKV_PLANE)     // 18432 B (K + V)
#define ATT_SMEM (AQ_PLANE + 2*AKV_STAGE)  // 55296 B

__global__ __launch_bounds__(256, 2) void attn_tc(
    const __half* __restrict__ Qh, const __half* __restrict__ Kh,
    const __half* __restrict__ Vh,
    const float* __restrict__ bias, const float* __restrict__ mask,
    __half* __restrict__ Chi, __half* __restrict__ Clo)
{
    const uint32_t smb = smem_u32(dynsmem);
    const int tid = threadIdx.x, lane = tid & 31, wid = tid >> 5;
    const int bh = blockIdx.y;
    const int b  = bh >> 4, h = bh & 15;
    const int q0 = blockIdx.x * 128;
    const int wr = wid * 16;
    const int r0 = lane >> 2, cq = (lane & 3) * 2;

    const __half* Qb = Qh + (size_t)bh * LL * DKK;
    const __half* KVpl[2] = {Kh + (size_t)bh * LL * DKK, Vh + (size_t)bh * LL * DKK};
    const float* brow0 = bias + ((size_t)bh * LL + (q0 + wr + r0)) * LL;
    const float* brow1 = brow0 + 8 * (size_t)LL;
    const float* maskb = mask + (size_t)b * LL;

    // one KV tile = 2 planes x 64 rows x 8 segs(16B) = 1024 cp16
    auto issue_kv = [&](int kt) {
        const uint32_t sbase = smb + AQ_PLANE + (kt & 1) * AKV_STAGE;
        const int k0 = kt * 64;
        #pragma unroll
        for (int it = 0; it < 4; it++) {
            const int idx = tid + it * 256;
            const int pl  = idx >> 9;
            const int r   = (idx >> 3) & 63;
            const int seg = idx & 7;
            cp16(sbase + pl * AKV_PLANE + r * AP + seg * 16,
                 KVpl[pl] + (size_t)(k0 + r) * DKK + seg * 8);
        }
    };

    // prologue: Q (128 rows x 8 segs = 1024) + KV tile 0
    #pragma unroll
    for (int it = 0; it < 4; it++) {
        const int idx = tid + it * 256;
        const int r   = (idx >> 3) & 127;
        const int seg = idx & 7;
        cp16(smb + r * AP + seg * 16,
             Qb + (size_t)(q0 + r) * DKK + seg * 8);
    }
    issue_kv(0);
    CP_COMMIT();

    float m_i[2] = {-1e30f, -1e30f}, l_i[2] = {0.f, 0.f};
    float oacc[8][4];
    #pragma unroll
    for (int j = 0; j < 8; j++)
        #pragma unroll
        for (int q = 0; q < 4; q++) oacc[j][q] = 0.f;

    for (int kt = 0; kt < LL/64; kt++) {
        const int k0 = kt * 64;
        CP_WAIT0();
        __syncthreads();
        if (kt + 1 < LL/64) { issue_kv(kt + 1); CP_COMMIT(); }

        const uint32_t kvK = smb + AQ_PLANE + (kt & 1) * AKV_STAGE;
        const uint32_t kvV = kvK + AKV_PLANE;

        // ---- S init = bias + mask ----
        float sacc[8][4];
        #pragma unroll
        for (int j = 0; j < 8; j++) {
            const int kc = k0 + j*8 + cq;
            float2 bz0 = *(const float2*)&brow0[kc];
            float2 bz1 = *(const float2*)&brow1[kc];
            float2 mz  = *(const float2*)&maskb[kc];
            sacc[j][0] = bz0.x + mz.x;
            sacc[j][1] = bz0.y + mz.y;
            sacc[j][2] = bz1.x + mz.x;
            sacc[j][3] = bz1.y + mz.y;
        }

        // ---- S += Q K^T  (1 chain) ----
        #pragma unroll
        for (int t = 0; t < 4; t++) {
            const uint32_t qoff = (lane & 15) * AP + (lane >> 4) * 16 + t * 32;
            uint32_t qa[4];
            ldsm4(qa, smb + wr * AP + qoff);
            #pragma unroll
            for (int jp = 0; jp < 4; jp++) {
                uint32_t kb[4];
                ldsm4(kb, kvK + (jp*16) * AP + qoff);
                mma_f16(sacc[2*jp],   qa, kb[0], kb[2]);
                mma_f16(sacc[2*jp+1], qa, kb[1], kb[3]);
            }
        }

        // ---- row max ----
        float mx0 = -1e30f, mx1 = -1e30f;
        #pragma unroll
        for (int j = 0; j < 8; j++) {
            mx0 = fmaxf(mx0, fmaxf(sacc[j][0], sacc[j][1]));
            mx1 = fmaxf(mx1, fmaxf(sacc[j][2], sacc[j][3]));
        }
        mx0 = fmaxf(mx0, __shfl_xor_sync(0xffffffffu, mx0, 1));
        mx0 = fmaxf(mx0, __shfl_xor_sync(0xffffffffu, mx0, 2));
        mx1 = fmaxf(mx1, __shfl_xor_sync(0xffffffffu, mx1, 1));
        mx1 = fmaxf(mx1, __shfl_xor_sync(0xffffffffu, mx1, 2));

        const float mn0 = fmaxf(m_i[0], mx0);
        const float mn1 = fmaxf(m_i[1], mx1);
        const float corr0 = __expf(m_i[0] - mn0);
        const float corr1 = __expf(m_i[1] - mn1);
        m_i[0] = mn0; m_i[1] = mn1;

        // ---- exp + round P to fp16; sum the ROUNDED values ----
        uint32_t ph[4][4];
        float rs0 = 0.f, rs1 = 0.f;
        #pragma unroll
        for (int j = 0; j < 8; j++) {
            __half h0 = __float2half(__expf(sacc[j][0] - mn0));
            __half h1 = __float2half(__expf(sacc[j][1] - mn0));
            __half h2 = __float2half(__expf(sacc[j][2] - mn1));
            __half h3 = __float2half(__expf(sacc[j][3] - mn1));
            rs0 += __half2float(h0) + __half2float(h1);
            rs1 += __half2float(h2) + __half2float(h3);
            const int t = j >> 1, s = (j & 1) * 2;
            ph[t][s+0] = pack_h2(h0, h1);
            ph[t][s+1] = pack_h2(h2, h3);
        }
        rs0 += __shfl_xor_sync(0xffffffffu, rs0, 1);
        rs0 += __shfl_xor_sync(0xffffffffu, rs0, 2);
        rs1 += __shfl_xor_sync(0xffffffffu, rs1, 1);
        rs1 += __shfl_xor_sync(0xffffffffu, rs1, 2);
        l_i[0] = l_i[0] * corr0 + rs0;
        l_i[1] = l_i[1] * corr1 + rs1;

        #pragma unroll
        for (int j = 0; j < 8; j++) {
            oacc[j][0] *= corr0; oacc[j][1] *= corr0;
            oacc[j][2] *= corr1; oacc[j][3] *= corr1;
        }

        // ---- O += P V  (1 chain) ----
        #pragma unroll
        for (int j = 0; j < 8; j++) {
            #pragma unroll
            for (int tp = 0; tp < 2; tp++) {
                const uint32_t va = (tp*32 + lane) * AP + j * 16;
                uint32_t vh[4];
                ldsm4t(vh, kvV + va);
                mma_f16(oacc[j], ph[2*tp],   vh[0], vh[1]);
                mma_f16(oacc[j], ph[2*tp+1], vh[2], vh[3]);
            }
        }
    }

    // ---- epilogue: ctx fp16 hi/lo planes (exact pair), (B*L, DM) layout ----
    const float inv0 = 1.0f / l_i[0];
    const float inv1 = 1.0f / l_i[1];
    const size_t row0 = (size_t)(b * LL + q0 + wr + r0);
    const size_t row1 = row0 + 8;
    #pragma unroll
    for (int j = 0; j < 8; j++) {
        const int col = h * DKK + j * 8 + cq;
        store_hilo_f16(Chi, Clo, row0 * DM + col, oacc[j][0] * inv0, oacc[j][1] * inv0);
        store_hilo_f16(Chi, Clo, row1 * DM + col, oacc[j][2] * inv1, oacc[j][3] * inv1);
    }
}

// ---------------------------------------------------------------------------
extern "C" void kernel_launch(void* const* d_in, const int* in_sizes, int n_in,
                              void* d_out, int out_size)
{
    const float* x    = (const float*)d_in[0];
    const float* Wq   = (const float*)d_in[1];
    const float* Wk   = (const float*)d_in[2];
    const float* Wv   = (const float*)d_in[3];
    const float* Wo   = (const float*)d_in[4];
    const float* bias = (const float*)d_in[5];
    const float* mask = (const float*)d_in[6];
    float* out = (float*)d_out;

    __half *xhi, *xlo, *wq, *wk, *wv, *wo, *qhf, *khf, *vhf, *chi, *clo;
    cudaGetSymbolAddress((void**)&xhi, g_xhi); cudaGetSymbolAddress((void**)&xlo, g_xlo);
    cudaGetSymbolAddress((void**)&wq, g_wq);   cudaGetSymbolAddress((void**)&wk, g_wk);
    cudaGetSymbolAddress((void**)&wv, g_wv);   cudaGetSymbolAddress((void**)&wo, g_wo);
    cudaGetSymbolAddress((void**)&qhf, g_qhf); cudaGetSymbolAddress((void**)&khf, g_khf);
    cudaGetSymbolAddress((void**)&vhf, g_vhf);
    cudaGetSymbolAddress((void**)&chi, g_chi); cudaGetSymbolAddress((void**)&clo, g_clo);

    const int nx4 = MROWS * DM / 4;
    const int nw4 = DM * DM / 4;
    split_f16<<<(nx4 + 255) / 256, 256>>>(x, xhi, xlo, nx4);
    conv_f16<<<(nw4 + 255) / 256, 256>>>(Wq, wq, nw4, 0.125f);  // fold 1/sqrt(dk)
    conv_f16<<<(nw4 + 255) / 256, 256>>>(Wk, wk, nw4, 1.0f);
    conv_f16<<<(nw4 + 255) / 256, 256>>>(Wv, wv, nw4, 1.0f);
    conv_f16<<<(nw4 + 255) / 256, 256>>>(Wo, wo, nw4, 1.0f);

    cudaFuncSetAttribute(gemm_tc, cudaFuncAttributeMaxDynamicSharedMemorySize, GEMM_SMEM);
    cudaFuncSetAttribute(attn_tc, cudaFuncAttributeMaxDynamicSharedMemorySize, ATT_SMEM);

    const dim3 ggrid(DM / 128, MROWS / 128);   // (8, 32)
    gemm_tc<<<ggrid, 256, GEMM_SMEM>>>(xhi, xlo, wq, nullptr, qhf, 2);
    gemm_tc<<<ggrid, 256, GEMM_SMEM>>>(xhi, xlo, wk, nullptr, khf, 2);
    gemm_tc<<<ggrid, 256, GEMM_SMEM>>>(xhi, xlo, wv, nullptr, vhf, 2);

    attn_tc<<<dim3(LL / 128, BB * HH), 256, ATT_SMEM>>>(
        qhf, khf, vhf, bias, mask, chi, clo);

    gemm_tc<<<ggrid, 256, GEMM_SMEM>>>(chi, clo, wo, out, nullptr, 0);
}

// round 15
// speedup vs baseline: 2.3547x; 1.3379x over previous
#include <cuda_runtime.h>
#include <cuda_fp16.h>
#include <math.h>
#include <cstdint>

#define BB   2
#define LL   2048
#define DM   1024
#define HH   16
#define DKK  64
#define MROWS (BB*LL)

// ---------------- scratch ----------------
__device__ __half g_xf[(size_t)MROWS*DM];
__device__ __half g_wq[(size_t)DM*DM];
__device__ __half g_wk[(size_t)DM*DM];
__device__ __half g_wv[(size_t)DM*DM];
__device__ __half g_wo[(size_t)DM*DM];
__device__ __half g_qhf[(size_t)BB*HH*LL*DKK];
__device__ __half g_khf[(size_t)BB*HH*LL*DKK];
__device__ __half g_vhf[(size_t)BB*HH*LL*DKK];
__device__ __half g_ctx[(size_t)MROWS*DM];

// ---------------- helpers ----------------
__device__ __forceinline__ uint32_t smem_u32(const void* p) {
    uint32_t a;
    asm("{ .reg .u64 t; cvta.to.shared.u64 t, %1; cvt.u32.u64 %0, t; }" : "=r"(a) : "l"(p));
    return a;
}
__device__ __forceinline__ void ldsm4(uint32_t* r, uint32_t a) {
    asm volatile("ldmatrix.sync.aligned.m8n8.x4.shared.b16 {%0,%1,%2,%3}, [%4];"
        : "=r"(r[0]), "=r"(r[1]), "=r"(r[2]), "=r"(r[3]) : "r"(a));
}
__device__ __forceinline__ void ldsm4t(uint32_t* r, uint32_t a) {
    asm volatile("ldmatrix.sync.aligned.m8n8.x4.trans.shared.b16 {%0,%1,%2,%3}, [%4];"
        : "=r"(r[0]), "=r"(r[1]), "=r"(r[2]), "=r"(r[3]) : "r"(a));
}
__device__ __forceinline__ void mma_f16(float* c, const uint32_t* a, uint32_t b0, uint32_t b1) {
    asm volatile(
        "mma.sync.aligned.m16n8k16.row.col.f32.f16.f16.f32 "
        "{%0,%1,%2,%3}, {%4,%5,%6,%7}, {%8,%9}, {%0,%1,%2,%3};"
        : "+f"(c[0]), "+f"(c[1]), "+f"(c[2]), "+f"(c[3])
        : "r"(a[0]), "r"(a[1]), "r"(a[2]), "r"(a[3]), "r"(b0), "r"(b1));
}
__device__ __forceinline__ void cp16(uint32_t dst, const void* src) {
    asm volatile("cp.async.cg.shared.global [%0], [%1], 16;" :: "r"(dst), "l"(src));
}
#define CP_COMMIT() asm volatile("cp.async.commit_group;" ::: "memory")
#define CP_WAIT0()  asm volatile("cp.async.wait_group 0;" ::: "memory")

__device__ __forceinline__ uint32_t pack_h2(__half a, __half b) {
    __half2 t{a, b};
    return *reinterpret_cast<uint32_t*>(&t);
}

extern __shared__ char dynsmem[];

// ---------------------------------------------------------------------------
// conv: fp32 -> (scale*) fp16 single plane
// ---------------------------------------------------------------------------
__global__ __launch_bounds__(256) void conv_f16(
    const float* __restrict__ in, __half* __restrict__ out, int n4, float scale)
{
    int i = blockIdx.x * blockDim.x + threadIdx.x;
    if (i >= n4) return;
    float4 v = ((const float4*)in)[i];
    ((__half2*)out)[2*i]   = {__float2half(v.x * scale), __float2half(v.y * scale)};
    ((__half2*)out)[2*i+1] = {__float2half(v.z * scale), __float2half(v.w * scale)};
}

// fused conversion of the 4 weight matrices (Wq scaled by 1/sqrt(dk))
#define NW4 (DM*DM/4)    // 262144 = 1<<18
__global__ __launch_bounds__(256) void conv_w4(
    const float* __restrict__ Wq, const float* __restrict__ Wk,
    const float* __restrict__ Wv, const float* __restrict__ Wo,
    __half* __restrict__ wq, __half* __restrict__ wk,
    __half* __restrict__ wv, __half* __restrict__ wo)
{
    int i = blockIdx.x * blockDim.x + threadIdx.x;
    if (i >= 4 * NW4) return;
    const int pl = i >> 18, off = i & (NW4 - 1);
    const float* src = (pl == 0) ? Wq : (pl == 1) ? Wk : (pl == 2) ? Wv : Wo;
    __half* dst = (pl == 0) ? wq : (pl == 1) ? wk : (pl == 2) ? wv : wo;
    const float s = (pl == 0) ? 0.125f : 1.0f;
    float4 v = ((const float4*)src)[off];
    ((__half2*)dst)[2*off]   = {__float2half(v.x * s), __float2half(v.y * s)};
    ((__half2*)dst)[2*off+1] = {__float2half(v.z * s), __float2half(v.w * s)};
}

// ---------------------------------------------------------------------------
// HMMA fp16 NT GEMM, single chain: C = A @ W^T, fp32 accum.
// cp.async 2-stage, K-chunk 32. Block 128x128, 8 warps (2M x 4N).
// mode 0: fp32 row-major out; mode 2: fp16 head-layout out.
// ---------------------------------------------------------------------------
#define GP 80
#define G_PLANE (128*GP)            // 10240 B
#define G_STAGE (2*G_PLANE)         // 20480 B (A, W)
#define GEMM_SMEM (2*G_STAGE)       // 40960 B

__global__ __launch_bounds__(256, 2) void gemm_tc(
    const __half* __restrict__ A, const __half* __restrict__ W,
    float* __restrict__ Cf, __half* __restrict__ Hf, int mode)
{
    const uint32_t smb = smem_u32(dynsmem);
    const int tid = threadIdx.x, lane = tid & 31, wid = tid >> 5;
    const int wm = wid >> 2, wn = wid & 3;
    const int m0 = blockIdx.y * 128, n0 = blockIdx.x * 128;
    const int r0 = lane >> 2, cq = (lane & 3) * 2;

    const __half* plane_src[2] = {A, W};
    const int   plane_row0[2] = {m0, n0};

    // one chunk = 2 planes x 128 rows x 4 segs(16B) = 1024 cp16
    auto issue_chunk = [&](int kc) {
        const uint32_t sbase = smb + (kc & 1) * G_STAGE;
        #pragma unroll
        for (int it = 0; it < 4; it++) {
            const int idx = tid + it * 256;        // 0..1023
            const int pl  = idx >> 9;
            const int r   = (idx >> 2) & 127;
            const int seg = idx & 3;
            cp16(sbase + pl * G_PLANE + r * GP + seg * 16,
                 plane_src[pl] + (size_t)(plane_row0[pl] + r) * DM + kc * 32 + seg * 8);
        }
    };

    float acc[4][4][4];
    #pragma unroll
    for (int i = 0; i < 4; i++)
        #pragma unroll
        for (int j = 0; j < 4; j++)
            #pragma unroll
            for (int q = 0; q < 4; q++) acc[i][j][q] = 0.f;

    issue_chunk(0);
    CP_COMMIT();

    for (int kc = 0; kc < 32; kc++) {
        CP_WAIT0();
        __syncthreads();
        if (kc + 1 < 32) { issue_chunk(kc + 1); CP_COMMIT(); }

        const uint32_t sbase = smb + (kc & 1) * G_STAGE;
        #pragma unroll
        for (int t = 0; t < 2; t++) {
            const uint32_t qoff = (lane & 15) * GP + (lane >> 4) * 16 + t * 32;
            uint32_t ah[4][4];
            #pragma unroll
            for (int mf = 0; mf < 4; mf++)
                ldsm4(ah[mf], sbase + (wm*64 + mf*16) * GP + qoff);
            #pragma unroll
            for (int jp = 0; jp < 2; jp++) {
                uint32_t bh[4];
                ldsm4(bh, sbase + G_PLANE + (wn*32 + jp*16) * GP + qoff);
                #pragma unroll
                for (int mf = 0; mf < 4; mf++) {
                    mma_f16(acc[mf][2*jp],   ah[mf], bh[0], bh[2]);
                    mma_f16(acc[mf][2*jp+1], ah[mf], bh[1], bh[3]);
                }
            }
        }
    }

    #pragma unroll
    for (int mf = 0; mf < 4; mf++) {
        const int mr = m0 + wm*64 + mf*16 + r0;
        #pragma unroll
        for (int jf = 0; jf < 4; jf++) {
            const int col = n0 + wn*32 + jf*8 + cq;
            if (mode == 0) {
                *(float2*)&Cf[(size_t)mr * DM + col] =
                    make_float2(acc[mf][jf][0], acc[mf][jf][1]);
                *(float2*)&Cf[(size_t)(mr+8) * DM + col] =
                    make_float2(acc[mf][jf][2], acc[mf][jf][3]);
            } else {
                const int h = col >> 6, d = col & 63;
                const int b0_ = mr >> 11, l0 = mr & 2047;
                const size_t i0 = (((size_t)(b0_*HH + h) * LL + l0) * DKK + d);
                const int mr1 = mr + 8;
                const int b1_ = mr1 >> 11, l1 = mr1 & 2047;
                const size_t i1 = (((size_t)(b1_*HH + h) * LL + l1) * DKK + d);
                *(__half2*)&Hf[i0] = __half2{__float2half(acc[mf][jf][0]),
                                             __float2half(acc[mf][jf][1])};
                *(__half2*)&Hf[i1] = __half2{__float2half(acc[mf][jf][2]),
                                             __float2half(acc[mf][jf][3])};
            }
        }
    }
}

// ---------------------------------------------------------------------------
// HMMA fp16 flash attention, single-plane Q/K/P/V (1+1 chains).
// Q pre-scaled by 1/sqrt(dk) (folded into Wq). Bias+mask preload into sacc.
// Normalization uses the ROUNDED P so rounding partially cancels in the ratio.
// Grid (L/128, B*H), 8 warps; warp = 16 q-rows x 64-key tile.
// ---------------------------------------------------------------------------
#define AP 144
#define AQ_PLANE (128*AP)           // 18432 B
#define AKV_PLANE (64*AP)           // 9216 B
#define AKV_STAGE (2*AKV_PLANE)     // 18432 B (K + V)
#define ATT_SMEM (AQ_PLANE + 2*AKV_STAGE)  // 55296 B

__global__ __launch_bounds__(256, 2) void attn_tc(
    const __half* __restrict__ Qh, const __half* __restrict__ Kh,
    const __half* __restrict__ Vh,
    const float* __restrict__ bias, const float* __restrict__ mask,
    __half* __restrict__ Ctx)
{
    const uint32_t smb = smem_u32(dynsmem);
    const int tid = threadIdx.x, lane = tid & 31, wid = tid >> 5;
    const int bh = blockIdx.y;
    const int b  = bh >> 4, h = bh & 15;
    const int q0 = blockIdx.x * 128;
    const int wr = wid * 16;
    const int r0 = lane >> 2, cq = (lane & 3) * 2;

    const __half* Qb = Qh + (size_t)bh * LL * DKK;
    const __half* KVpl[2] = {Kh + (size_t)bh * LL * DKK, Vh + (size_t)bh * LL * DKK};
    const float* brow0 = bias + ((size_t)bh * LL + (q0 + wr + r0)) * LL;
    const float* brow1 = brow0 + 8 * (size_t)LL;
    const float* maskb = mask + (size_t)b * LL;

    auto issue_kv = [&](int kt) {
        const uint32_t sbase = smb + AQ_PLANE + (kt & 1) * AKV_STAGE;
        const int k0 = kt * 64;
        #pragma unroll
        for (int it = 0; it < 4; it++) {
            const int idx = tid + it * 256;
            const int pl  = idx >> 9;
            const int r   = (idx >> 3) & 63;
            const int seg = idx & 7;
            cp16(sbase + pl * AKV_PLANE + r * AP + seg * 16,
                 KVpl[pl] + (size_t)(k0 + r) * DKK + seg * 8);
        }
    };

    // prologue: Q (128 rows x 8 segs = 1024) + KV tile 0
    #pragma unroll
    for (int it = 0; it < 4; it++) {
        const int idx = tid + it * 256;
        const int r   = (idx >> 3) & 127;
        const int seg = idx & 7;
        cp16(smb + r * AP + seg * 16,
             Qb + (size_t)(q0 + r) * DKK + seg * 8);
    }
    issue_kv(0);
    CP_COMMIT();

    float m_i[2] = {-1e30f, -1e30f}, l_i[2] = {0.f, 0.f};
    float oacc[8][4];
    #pragma unroll
    for (int j = 0; j < 8; j++)
        #pragma unroll
        for (int q = 0; q < 4; q++) oacc[j][q] = 0.f;

    for (int kt = 0; kt < LL/64; kt++) {
        const int k0 = kt * 64;
        CP_WAIT0();
        __syncthreads();
        if (kt + 1 < LL/64) { issue_kv(kt + 1); CP_COMMIT(); }

        const uint32_t kvK = smb + AQ_PLANE + (kt & 1) * AKV_STAGE;
        const uint32_t kvV = kvK + AKV_PLANE;

        // ---- S init = bias + mask ----
        float sacc[8][4];
        #pragma unroll
        for (int j = 0; j < 8; j++) {
            const int kc = k0 + j*8 + cq;
            float2 bz0 = *(const float2*)&brow0[kc];
            float2 bz1 = *(const float2*)&brow1[kc];
            float2 mz  = *(const float2*)&maskb[kc];
            sacc[j][0] = bz0.x + mz.x;
            sacc[j][1] = bz0.y + mz.y;
            sacc[j][2] = bz1.x + mz.x;
            sacc[j][3] = bz1.y + mz.y;
        }

        // ---- S += Q K^T  (1 chain) ----
        #pragma unroll
        for (int t = 0; t < 4; t++) {
            const uint32_t qoff = (lane & 15) * AP + (lane >> 4) * 16 + t * 32;
            uint32_t qa[4];
            ldsm4(qa, smb + wr * AP + qoff);
            #pragma unroll
            for (int jp = 0; jp < 4; jp++) {
                uint32_t kb[4];
                ldsm4(kb, kvK + (jp*16) * AP + qoff);
                mma_f16(sacc[2*jp],   qa, kb[0], kb[2]);
                mma_f16(sacc[2*jp+1], qa, kb[1], kb[3]);
            }
        }

        // ---- row max ----
        float mx0 = -1e30f, mx1 = -1e30f;
        #pragma unroll
        for (int j = 0; j < 8; j++) {
            mx0 = fmaxf(mx0, fmaxf(sacc[j][0], sacc[j][1]));
            mx1 = fmaxf(mx1, fmaxf(sacc[j][2], sacc[j][3]));
        }
        mx0 = fmaxf(mx0, __shfl_xor_sync(0xffffffffu, mx0, 1));
        mx0 = fmaxf(mx0, __shfl_xor_sync(0xffffffffu, mx0, 2));
        mx1 = fmaxf(mx1, __shfl_xor_sync(0xffffffffu, mx1, 1));
        mx1 = fmaxf(mx1, __shfl_xor_sync(0xffffffffu, mx1, 2));

        const float mn0 = fmaxf(m_i[0], mx0);
        const float mn1 = fmaxf(m_i[1], mx1);
        const float corr0 = __expf(m_i[0] - mn0);
        const float corr1 = __expf(m_i[1] - mn1);
        m_i[0] = mn0; m_i[1] = mn1;

        // ---- exp + round P to fp16; sum the ROUNDED values ----
        uint32_t ph[4][4];
        float rs0 = 0.f, rs1 = 0.f;
        #pragma unroll
        for (int j = 0; j < 8; j++) {
            __half h0 = __float2half(__expf(sacc[j][0] - mn0));
            __half h1 = __float2half(__expf(sacc[j][1] - mn0));
            __half h2 = __float2half(__expf(sacc[j][2] - mn1));
            __half h3 = __float2half(__expf(sacc[j][3] - mn1));
            rs0 += __half2float(h0) + __half2float(h1);
            rs1 += __half2float(h2) + __half2float(h3);
            const int t = j >> 1, s = (j & 1) * 2;
            ph[t][s+0] = pack_h2(h0, h1);
            ph[t][s+1] = pack_h2(h2, h3);
        }
        rs0 += __shfl_xor_sync(0xffffffffu, rs0, 1);
        rs0 += __shfl_xor_sync(0xffffffffu, rs0, 2);
        rs1 += __shfl_xor_sync(0xffffffffu, rs1, 1);
        rs1 += __shfl_xor_sync(0xffffffffu, rs1, 2);
        l_i[0] = l_i[0] * corr0 + rs0;
        l_i[1] = l_i[1] * corr1 + rs1;

        #pragma unroll
        for (int j = 0; j < 8; j++) {
            oacc[j][0] *= corr0; oacc[j][1] *= corr0;
            oacc[j][2] *= corr1; oacc[j][3] *= corr1;
        }

        // ---- O += P V  (1 chain) ----
        #pragma unroll
        for (int j = 0; j < 8; j++) {
            #pragma unroll
            for (int tp = 0; tp < 2; tp++) {
                const uint32_t va = (tp*32 + lane) * AP + j * 16;
                uint32_t vh[4];
                ldsm4t(vh, kvV + va);
                mma_f16(oacc[j], ph[2*tp],   vh[0], vh[1]);
                mma_f16(oacc[j], ph[2*tp+1], vh[2], vh[3]);
            }
        }
    }

    // ---- epilogue: ctx fp16 single plane, (B*L, DM) layout ----
    const float inv0 = 1.0f / l_i[0];
    const float inv1 = 1.0f / l_i[1];
    const size_t row0 = (size_t)(b * LL + q0 + wr + r0);
    const size_t row1 = row0 + 8;
    #pragma unroll
    for (int j = 0; j < 8; j++) {
        const int col = h * DKK + j * 8 + cq;
        *(__half2*)&Ctx[row0 * DM + col] =
            __half2{__float2half(oacc[j][0] * inv0), __float2half(oacc[j][1] * inv0)};
        *(__half2*)&Ctx[row1 * DM + col] =
            __half2{__float2half(oacc[j][2] * inv1), __float2half(oacc[j][3] * inv1)};
    }
}

// ---------------------------------------------------------------------------
extern "C" void kernel_launch(void* const* d_in, const int* in_sizes, int n_in,
                              void* d_out, int out_size)
{
    const float* x    = (const float*)d_in[0];
    const float* Wq   = (const float*)d_in[1];
    const float* Wk   = (const float*)d_in[2];
    const float* Wv   = (const float*)d_in[3];
    const float* Wo   = (const float*)d_in[4];
    const float* bias = (const float*)d_in[5];
    const float* mask = (const float*)d_in[6];
    float* out = (float*)d_out;

    __half *xf, *wq, *wk, *wv, *wo, *qhf, *khf, *vhf, *ctx;
    cudaGetSymbolAddress((void**)&xf, g_xf);
    cudaGetSymbolAddress((void**)&wq, g_wq);   cudaGetSymbolAddress((void**)&wk, g_wk);
    cudaGetSymbolAddress((void**)&wv, g_wv);   cudaGetSymbolAddress((void**)&wo, g_wo);
    cudaGetSymbolAddress((void**)&qhf, g_qhf); cudaGetSymbolAddress((void**)&khf, g_khf);
    cudaGetSymbolAddress((void**)&vhf, g_vhf); cudaGetSymbolAddress((void**)&ctx, g_ctx);

    const int nx4 = MROWS * DM / 4;
    conv_f16<<<(nx4 + 255) / 256, 256>>>(x, xf, nx4, 1.0f);
    conv_w4<<<(4 * NW4 + 255) / 256, 256>>>(Wq, Wk, Wv, Wo, wq, wk, wv, wo);

    cudaFuncSetAttribute(gemm_tc, cudaFuncAttributeMaxDynamicSharedMemorySize, GEMM_SMEM);
    cudaFuncSetAttribute(attn_tc, cudaFuncAttributeMaxDynamicSharedMemorySize, ATT_SMEM);

    const dim3 ggrid(DM / 128, MROWS / 128);   // (8, 32)
    gemm_tc<<<ggrid, 256, GEMM_SMEM>>>(xf, wq, nullptr, qhf, 2);
    gemm_tc<<<ggrid, 256, GEMM_SMEM>>>(xf, wk, nullptr, khf, 2);
    gemm_tc<<<ggrid, 256, GEMM_SMEM>>>(xf, wv, nullptr, vhf, 2);

    attn_tc<<<dim3(LL / 128, BB * HH), 256, ATT_SMEM>>>(
        qhf, khf, vhf, bias, mask, ctx);

    gemm_tc<<<ggrid, 256, GEMM_SMEM>>>(ctx, wo, out, nullptr, 0);
}